// round 1
// baseline (speedup 1.0000x reference)
#include <cuda_runtime.h>
#include <cuda_bf16.h>
#include <math.h>

// ---------------- problem constants (static per reference) ----------------
constexpr int B_   = 2;
constexpr int E_   = 256;
constexpr int NH_  = 8;
constexpr int D_   = 32;
constexpr int NL_  = 4;
constexpr int NP_  = 4;
constexpr int LQ_  = 17821;          // == Lin
constexpr int MROWS = B_ * LQ_;      // 35642

// level geometry
__device__ __constant__ int c_HS[4] = {100, 50, 25, 13};
__device__ __constant__ int c_WS[4] = {134, 67, 34, 17};
__device__ __constant__ int c_ST[4] = {0, 13400, 16750, 17600};

// ---------------- scratch (device globals; no allocation) -----------------
__device__ float g_v[(size_t)MROWS * 256];     // projected value (b,pos,h,d)
__device__ float g_off[(size_t)MROWS * 256];   // raw offsets per (b,q)
__device__ float g_attn[(size_t)MROWS * 128];  // raw attn logits per (b,q)
__device__ float g_samp[(size_t)MROWS * 256];  // sampled output (b,q,h,d)

// ---------------------------------------------------------------------------
// Tiled SGEMM: C[M,N] = A[M,K] @ W[K,N] + bias[N]
// AMODE 0: A row m at A[m*K + k]
// AMODE 1: A is (rows, B_, K) with m = b*LQ_ + r  -> A[(r*B_ + b)*K + k]
// CMODE 0: C row m at C[m*N + n]
// CMODE 1: C is (rows, B_, N) with m = b*LQ_ + r  -> C[(r*B_ + b)*N + n]
// BM=128, BN=128, BK=8, 256 threads, 8x8 per thread.
// N must be a multiple of 128; K a multiple of 8.
// ---------------------------------------------------------------------------
template <int AMODE, int CMODE>
__global__ void __launch_bounds__(256, 2)
sgemm_kernel(const float* __restrict__ A, const float* __restrict__ W,
             const float* __restrict__ bias, float* __restrict__ C,
             int M, int N, int K)
{
    constexpr int BM = 128, BN = 128, BK = 8;
    __shared__ float As[BK][BM + 4];
    __shared__ float Bs[BK][BN];

    const int tid = threadIdx.x;
    const int bm  = blockIdx.y * BM;
    const int bn  = blockIdx.x * BN;

    const int tx = tid & 15;   // n-dir, 16
    const int ty = tid >> 4;   // m-dir, 16

    // A tile load mapping: 128 rows x 8 k = 1024 floats / 256 thr = float4 each
    const int a_row = tid >> 1;
    const int a_k   = (tid & 1) * 4;
    // B tile load: 8 k x 128 n
    const int b_k = tid >> 5;
    const int b_n = (tid & 31) * 4;

    float acc[8][8];
#pragma unroll
    for (int i = 0; i < 8; i++)
#pragma unroll
        for (int j = 0; j < 8; j++) acc[i][j] = 0.f;

    const int m_load = bm + a_row;
    const float* aptr = nullptr;
    if (m_load < M) {
        long ai;
        if (AMODE == 0) {
            ai = (long)m_load * K;
        } else {
            int r = m_load % LQ_;
            int b = m_load / LQ_;
            ai = ((long)r * B_ + b) * K;
        }
        aptr = A + ai + a_k;
    }

    for (int k0 = 0; k0 < K; k0 += BK) {
        float4 av = make_float4(0.f, 0.f, 0.f, 0.f);
        if (aptr) av = *reinterpret_cast<const float4*>(aptr + k0);
        As[a_k + 0][a_row] = av.x;
        As[a_k + 1][a_row] = av.y;
        As[a_k + 2][a_row] = av.z;
        As[a_k + 3][a_row] = av.w;

        float4 wv = *reinterpret_cast<const float4*>(W + (long)(k0 + b_k) * N + bn + b_n);
        *reinterpret_cast<float4*>(&Bs[b_k][b_n]) = wv;

        __syncthreads();

#pragma unroll
        for (int kk = 0; kk < BK; kk++) {
            float ar[8], br[8];
            float4 t0 = *reinterpret_cast<const float4*>(&As[kk][ty * 8]);
            float4 t1 = *reinterpret_cast<const float4*>(&As[kk][ty * 8 + 4]);
            ar[0] = t0.x; ar[1] = t0.y; ar[2] = t0.z; ar[3] = t0.w;
            ar[4] = t1.x; ar[5] = t1.y; ar[6] = t1.z; ar[7] = t1.w;
            float4 u0 = *reinterpret_cast<const float4*>(&Bs[kk][tx * 8]);
            float4 u1 = *reinterpret_cast<const float4*>(&Bs[kk][tx * 8 + 4]);
            br[0] = u0.x; br[1] = u0.y; br[2] = u0.z; br[3] = u0.w;
            br[4] = u1.x; br[5] = u1.y; br[6] = u1.z; br[7] = u1.w;
#pragma unroll
            for (int i = 0; i < 8; i++)
#pragma unroll
                for (int j = 0; j < 8; j++)
                    acc[i][j] = fmaf(ar[i], br[j], acc[i][j]);
        }
        __syncthreads();
    }

    // epilogue: bias + store
#pragma unroll
    for (int i = 0; i < 8; i++) {
        int mm = bm + ty * 8 + i;
        if (mm >= M) continue;
        long cbase;
        if (CMODE == 0) {
            cbase = (long)mm * N;
        } else {
            int r = mm % LQ_;
            int b = mm / LQ_;
            cbase = ((long)r * B_ + b) * N;
        }
#pragma unroll
        for (int j = 0; j < 8; j++) {
            int nn = bn + tx * 8 + j;
            C[cbase + nn] = acc[i][j] + bias[nn];
        }
    }
}

// ---------------------------------------------------------------------------
// Sampling kernel: one warp per (b, q, h); lane = d (0..31).
// Reads g_v, g_off, g_attn; writes g_samp[(b*Lq+q)*256 + h*32 + d].
// ---------------------------------------------------------------------------
__global__ void __launch_bounds__(256)
sample_kernel(const float* __restrict__ refp)
{
    const int w    = blockIdx.x * 8 + (threadIdx.x >> 5);
    const int lane = threadIdx.x & 31;
    if (w >= MROWS * NH_) return;
    const int h = w & 7;
    const int m = w >> 3;            // m = b*Lq + q
    const int b = m / LQ_;

    // per-lane raw offset value (layout within head slice: (l*4+p)*2 + c)
    const float offv = g_off[(long)m * 256 + h * 32 + lane];

    // attn logits: lanes 0..15 hold (l*4 + p)
    float attv = 0.f;
    if (lane < 16) attv = g_attn[(long)m * 128 + h * 16 + lane];

    // softmax over p within each group of 4 lanes
    float mx = attv;
    mx = fmaxf(mx, __shfl_xor_sync(0xffffffffu, mx, 1));
    mx = fmaxf(mx, __shfl_xor_sync(0xffffffffu, mx, 2));
    float e = expf(attv - mx);
    float s = e;
    s += __shfl_xor_sync(0xffffffffu, s, 1);
    s += __shfl_xor_sync(0xffffffffu, s, 2);
    const float wgt = e / s;

    float acc = 0.f;
    const long vb = (long)b * LQ_ * 256 + h * 32 + lane;

#pragma unroll
    for (int l = 0; l < NL_; l++) {
        const int   Wl = c_WS[l], Hl = c_HS[l];
        const float fw = (float)Wl, fh = (float)Hl;
        const float rx = __ldg(&refp[((long)m * NL_ + l) * 2 + 0]);
        const float ry = __ldg(&refp[((long)m * NL_ + l) * 2 + 1]);
        const long  lvbase = vb + (long)c_ST[l] * 256;

#pragma unroll
        for (int p = 0; p < NP_; p++) {
            const int oi = (l * 4 + p) * 2;
            const float ox = __shfl_sync(0xffffffffu, offv, oi);
            const float oy = __shfl_sync(0xffffffffu, offv, oi + 1);
            const float aw = __shfl_sync(0xffffffffu, wgt, l * 4 + p);

            const float locx = rx + ox / fw;
            const float locy = ry + oy / fh;
            const float x = locx * fw - 0.5f;
            const float y = locy * fh - 0.5f;

            const float x0f = floorf(x), y0f = floorf(y);
            const int   x0 = (int)x0f, y0 = (int)y0f;
            const float dx = x - x0f, dy = y - y0f;

            const float w00 = (1.f - dx) * (1.f - dy) * aw;
            const float w10 = dx * (1.f - dy) * aw;
            const float w01 = (1.f - dx) * dy * aw;
            const float w11 = dx * dy * aw;

            const bool vx0 = (x0 >= 0) && (x0 < Wl);
            const bool vx1 = (x0 + 1 >= 0) && (x0 + 1 < Wl);
            const bool vy0 = (y0 >= 0) && (y0 < Hl);
            const bool vy1 = (y0 + 1 >= 0) && (y0 + 1 < Hl);

            if (vy0 && vx0) acc = fmaf(w00, __ldg(&g_v[lvbase + (long)(y0 * Wl + x0) * 256]), acc);
            if (vy0 && vx1) acc = fmaf(w10, __ldg(&g_v[lvbase + (long)(y0 * Wl + x0 + 1) * 256]), acc);
            if (vy1 && vx0) acc = fmaf(w01, __ldg(&g_v[lvbase + (long)((y0 + 1) * Wl + x0) * 256]), acc);
            if (vy1 && vx1) acc = fmaf(w11, __ldg(&g_v[lvbase + (long)((y0 + 1) * Wl + x0 + 1) * 256]), acc);
        }
    }

    g_samp[(long)m * 256 + h * 32 + lane] = acc;
}

// ---------------------------------------------------------------------------
extern "C" void kernel_launch(void* const* d_in, const int* in_sizes, int n_in,
                              void* d_out, int out_size)
{
    const float* query = (const float*)d_in[0];   // (Lq, B, E)
    const float* value = (const float*)d_in[1];   // (Lin, B, E)
    const float* refp  = (const float*)d_in[2];   // (B, Lq, NL, 2)
    // d_in[3] = spatial_shapes (int64) — static, hardcoded
    const float* Wv    = (const float*)d_in[4];
    const float* bv    = (const float*)d_in[5];
    const float* Woff  = (const float*)d_in[6];
    const float* boff  = (const float*)d_in[7];
    const float* Wat   = (const float*)d_in[8];
    const float* bat   = (const float*)d_in[9];
    const float* Wout  = (const float*)d_in[10];
    const float* bout  = (const float*)d_in[11];
    float* out = (float*)d_out;

    float *pv, *poff, *pattn, *psamp;
    cudaGetSymbolAddress((void**)&pv,    g_v);
    cudaGetSymbolAddress((void**)&poff,  g_off);
    cudaGetSymbolAddress((void**)&pattn, g_attn);
    cudaGetSymbolAddress((void**)&psamp, g_samp);

    const int mtiles = (MROWS + 127) / 128;  // 279

    // 1) value projection: (B*Lin,256) @ (256,256)
    sgemm_kernel<1, 0><<<dim3(2, mtiles), 256>>>(value, Wv, bv, pv, MROWS, 256, 256);
    // 2) offsets: (B*Lq,256) @ (256,256)
    sgemm_kernel<1, 0><<<dim3(2, mtiles), 256>>>(query, Woff, boff, poff, MROWS, 256, 256);
    // 3) attn logits: (B*Lq,256) @ (256,128)
    sgemm_kernel<1, 0><<<dim3(1, mtiles), 256>>>(query, Wat, bat, pattn, MROWS, 128, 256);
    // 4) softmax + bilinear sampling
    sample_kernel<<<MROWS, 256>>>(refp);
    // 5) output projection, stored transposed to (Lq, B, E)
    sgemm_kernel<0, 1><<<dim3(2, mtiles), 256>>>(psamp, Wout, bout, out, MROWS, 256, 256);
}

// round 2
// speedup vs baseline: 1.7334x; 1.7334x over previous
#include <cuda_runtime.h>
#include <cuda_bf16.h>
#include <math.h>

// ---------------- problem constants (static per reference) ----------------
constexpr int B_   = 2;
constexpr int E_   = 256;
constexpr int NH_  = 8;
constexpr int D_   = 32;
constexpr int NL_  = 4;
constexpr int NP_  = 4;
constexpr int LQ_  = 17821;          // == Lin
constexpr int MROWS = B_ * LQ_;      // 35642

// level geometry
__device__ __constant__ int c_HS[4] = {100, 50, 25, 13};
__device__ __constant__ int c_WS[4] = {134, 67, 34, 17};
__device__ __constant__ int c_ST[4] = {0, 13400, 16750, 17600};

// ---------------- scratch (device globals; no allocation) -----------------
__device__ float g_v[(size_t)MROWS * 256];     // projected value (b,pos,h,d)
__device__ float g_off[(size_t)MROWS * 256];   // raw offsets per (b,q)
__device__ float g_attn[(size_t)MROWS * 128];  // raw attn logits per (b,q)
__device__ float g_samp[(size_t)MROWS * 256];  // sampled output (b,q,h,d)

// ---------------------------------------------------------------------------
// Tiled SGEMM: C[M,N] = A[M,K] @ W[K,N] + bias[N]
// AMODE 0: A row m at A[m*K + k]
// AMODE 1: A is (rows, B_, K) with m = b*LQ_ + r  -> A[(r*B_ + b)*K + k]
// CMODE 0: C row m at C[m*N + n]
// CMODE 1: C is (rows, B_, N) with m = b*LQ_ + r  -> C[(r*B_ + b)*N + n]
// BM=128, BN=128, BK=8, 256 threads, 8x8 per thread.
// ---------------------------------------------------------------------------
template <int AMODE, int CMODE>
__global__ void __launch_bounds__(256, 2)
sgemm_kernel(const float* __restrict__ A, const float* __restrict__ W,
             const float* __restrict__ bias, float* __restrict__ C,
             int M, int N, int K)
{
    constexpr int BM = 128, BN = 128, BK = 8;
    __shared__ float As[BK][BM + 4];
    __shared__ float Bs[BK][BN];

    const int tid = threadIdx.x;
    const int bm  = blockIdx.y * BM;
    const int bn  = blockIdx.x * BN;

    const int tx = tid & 15;   // n-dir, 16
    const int ty = tid >> 4;   // m-dir, 16

    const int a_row = tid >> 1;
    const int a_k   = (tid & 1) * 4;
    const int b_k = tid >> 5;
    const int b_n = (tid & 31) * 4;

    float acc[8][8];
#pragma unroll
    for (int i = 0; i < 8; i++)
#pragma unroll
        for (int j = 0; j < 8; j++) acc[i][j] = 0.f;

    const int m_load = bm + a_row;
    const float* aptr = nullptr;
    if (m_load < M) {
        int ai;
        if (AMODE == 0) {
            ai = m_load * K;
        } else {
            int r = m_load % LQ_;
            int b = m_load / LQ_;
            ai = (r * B_ + b) * K;
        }
        aptr = A + ai + a_k;
    }

    for (int k0 = 0; k0 < K; k0 += BK) {
        float4 av = make_float4(0.f, 0.f, 0.f, 0.f);
        if (aptr) av = *reinterpret_cast<const float4*>(aptr + k0);
        As[a_k + 0][a_row] = av.x;
        As[a_k + 1][a_row] = av.y;
        As[a_k + 2][a_row] = av.z;
        As[a_k + 3][a_row] = av.w;

        float4 wv = *reinterpret_cast<const float4*>(W + (k0 + b_k) * N + bn + b_n);
        *reinterpret_cast<float4*>(&Bs[b_k][b_n]) = wv;

        __syncthreads();

#pragma unroll
        for (int kk = 0; kk < BK; kk++) {
            float ar[8], br[8];
            float4 t0 = *reinterpret_cast<const float4*>(&As[kk][ty * 8]);
            float4 t1 = *reinterpret_cast<const float4*>(&As[kk][ty * 8 + 4]);
            ar[0] = t0.x; ar[1] = t0.y; ar[2] = t0.z; ar[3] = t0.w;
            ar[4] = t1.x; ar[5] = t1.y; ar[6] = t1.z; ar[7] = t1.w;
            float4 u0 = *reinterpret_cast<const float4*>(&Bs[kk][tx * 8]);
            float4 u1 = *reinterpret_cast<const float4*>(&Bs[kk][tx * 8 + 4]);
            br[0] = u0.x; br[1] = u0.y; br[2] = u0.z; br[3] = u0.w;
            br[4] = u1.x; br[5] = u1.y; br[6] = u1.z; br[7] = u1.w;
#pragma unroll
            for (int i = 0; i < 8; i++)
#pragma unroll
                for (int j = 0; j < 8; j++)
                    acc[i][j] = fmaf(ar[i], br[j], acc[i][j]);
        }
        __syncthreads();
    }

    // epilogue: bias + vectorized store
    float4 bia0 = *reinterpret_cast<const float4*>(&bias[bn + tx * 8]);
    float4 bia1 = *reinterpret_cast<const float4*>(&bias[bn + tx * 8 + 4]);
#pragma unroll
    for (int i = 0; i < 8; i++) {
        int mm = bm + ty * 8 + i;
        if (mm >= M) continue;
        int cbase;
        if (CMODE == 0) {
            cbase = mm * N;
        } else {
            int r = mm % LQ_;
            int b = mm / LQ_;
            cbase = (r * B_ + b) * N;
        }
        float4 o0, o1;
        o0.x = acc[i][0] + bia0.x; o0.y = acc[i][1] + bia0.y;
        o0.z = acc[i][2] + bia0.z; o0.w = acc[i][3] + bia0.w;
        o1.x = acc[i][4] + bia1.x; o1.y = acc[i][5] + bia1.y;
        o1.z = acc[i][6] + bia1.z; o1.w = acc[i][7] + bia1.w;
        *reinterpret_cast<float4*>(&C[cbase + bn + tx * 8])     = o0;
        *reinterpret_cast<float4*>(&C[cbase + bn + tx * 8 + 4]) = o1;
    }
}

// ---------------------------------------------------------------------------
// Sampling kernel v2: one warp per (b,q,half); each 8-lane group = one head,
// lane handles float4 of D. 32-bit indexing throughout.
// ---------------------------------------------------------------------------
__global__ void __launch_bounds__(256)
sample_kernel(const float* __restrict__ refp)
{
    const int w = blockIdx.x * 8 + (threadIdx.x >> 5);
    if (w >= MROWS * 2) return;
    const int lane = threadIdx.x & 31;
    const int m    = w >> 1;              // b*Lq + q
    const int half = w & 1;
    const int g    = lane >> 3;           // head group within warp
    const int sub  = lane & 7;            // float4 slot within head (D/4 = 8)
    const int h    = half * 4 + g;
    const int b    = (m >= LQ_) ? 1 : 0;

    // this lane owns samples s0=2*sub, s1=2*sub+1 of its head:
    // offsets (x,y) pairs and attn logits
    const float4 offv = *reinterpret_cast<const float4*>(&g_off[m * 256 + h * 32 + sub * 4]);
    const float2 lg   = *reinterpret_cast<const float2*>(&g_attn[m * 128 + h * 16 + sub * 2]);

    // softmax over NP=4 within each level: lanes (2l, 2l+1) hold the 4 logits
    float mx = fmaxf(lg.x, lg.y);
    mx = fmaxf(mx, __shfl_xor_sync(0xffffffffu, mx, 1));
    const float e0 = expf(lg.x - mx);
    const float e1 = expf(lg.y - mx);
    float s = e0 + e1;
    s += __shfl_xor_sync(0xffffffffu, s, 1);
    const float inv = 1.f / s;
    const float wg0 = e0 * inv;
    const float wg1 = e1 * inv;

    // reference points (identical across the warp; L1 broadcast)
    float rx[4], ry[4];
#pragma unroll
    for (int l = 0; l < 4; l++) {
        rx[l] = __ldg(&refp[(m * 4 + l) * 2 + 0]);
        ry[l] = __ldg(&refp[(m * 4 + l) * 2 + 1]);
    }

    const float4* __restrict__ v4 = reinterpret_cast<const float4*>(g_v);
    int base[4];
#pragma unroll
    for (int l = 0; l < 4; l++)
        base[l] = (b * LQ_ + c_ST[l]) * 64 + h * 8 + sub;

    float4 acc = make_float4(0.f, 0.f, 0.f, 0.f);
    const int grp = lane & 24;

#pragma unroll
    for (int sp = 0; sp < 16; sp++) {
        const int l = sp >> 2;
        const int owner = grp | (sp >> 1);
        const float ox = __shfl_sync(0xffffffffu, (sp & 1) ? offv.z : offv.x, owner);
        const float oy = __shfl_sync(0xffffffffu, (sp & 1) ? offv.w : offv.y, owner);
        const float aw = __shfl_sync(0xffffffffu, (sp & 1) ? wg1 : wg0, owner);

        const int Wl = c_WS[l], Hl = c_HS[l];
        // loc*W - 0.5 with loc = rx + ox/W  ==  rx*W + ox - 0.5
        const float x = fmaf(rx[l], (float)Wl, ox) - 0.5f;
        const float y = fmaf(ry[l], (float)Hl, oy) - 0.5f;
        const float xf = floorf(x), yf = floorf(y);
        const int x0 = (int)xf, y0 = (int)yf;
        const float dx = x - xf, dy = y - yf;

        float w11 = dx * dy * aw;
        float w10 = fmaf(dx, aw, -w11);   // dx*(1-dy)*aw
        float w01 = fmaf(dy, aw, -w11);   // (1-dx)*dy*aw
        float w00 = aw - w10 - w01 - w11; // (1-dx)*(1-dy)*aw

        const bool vx0 = (unsigned)x0       < (unsigned)Wl;
        const bool vx1 = (unsigned)(x0 + 1) < (unsigned)Wl;
        const bool vy0 = (unsigned)y0       < (unsigned)Hl;
        const bool vy1 = (unsigned)(y0 + 1) < (unsigned)Hl;
        if (!(vx0 && vy0)) w00 = 0.f;
        if (!(vx1 && vy0)) w10 = 0.f;
        if (!(vx0 && vy1)) w01 = 0.f;
        if (!(vx1 && vy1)) w11 = 0.f;

        const int x0c = min(max(x0, 0), Wl - 1);
        const int x1c = min(max(x0 + 1, 0), Wl - 1);
        const int y0c = min(max(y0, 0), Hl - 1);
        const int y1c = min(max(y0 + 1, 0), Hl - 1);

        const int r0 = base[l] + y0c * (Wl * 64);
        const int r1 = base[l] + y1c * (Wl * 64);

        const float4 v00 = __ldg(&v4[r0 + x0c * 64]);
        const float4 v10 = __ldg(&v4[r0 + x1c * 64]);
        const float4 v01 = __ldg(&v4[r1 + x0c * 64]);
        const float4 v11 = __ldg(&v4[r1 + x1c * 64]);

        acc.x = fmaf(w00, v00.x, acc.x); acc.y = fmaf(w00, v00.y, acc.y);
        acc.z = fmaf(w00, v00.z, acc.z); acc.w = fmaf(w00, v00.w, acc.w);
        acc.x = fmaf(w10, v10.x, acc.x); acc.y = fmaf(w10, v10.y, acc.y);
        acc.z = fmaf(w10, v10.z, acc.z); acc.w = fmaf(w10, v10.w, acc.w);
        acc.x = fmaf(w01, v01.x, acc.x); acc.y = fmaf(w01, v01.y, acc.y);
        acc.z = fmaf(w01, v01.z, acc.z); acc.w = fmaf(w01, v01.w, acc.w);
        acc.x = fmaf(w11, v11.x, acc.x); acc.y = fmaf(w11, v11.y, acc.y);
        acc.z = fmaf(w11, v11.z, acc.z); acc.w = fmaf(w11, v11.w, acc.w);
    }

    *reinterpret_cast<float4*>(&g_samp[m * 256 + h * 32 + sub * 4]) = acc;
}

// ---------------------------------------------------------------------------
extern "C" void kernel_launch(void* const* d_in, const int* in_sizes, int n_in,
                              void* d_out, int out_size)
{
    const float* query = (const float*)d_in[0];   // (Lq, B, E)
    const float* value = (const float*)d_in[1];   // (Lin, B, E)
    const float* refp  = (const float*)d_in[2];   // (B, Lq, NL, 2)
    // d_in[3] = spatial_shapes (int64) — static, hardcoded
    const float* Wv    = (const float*)d_in[4];
    const float* bv    = (const float*)d_in[5];
    const float* Woff  = (const float*)d_in[6];
    const float* boff  = (const float*)d_in[7];
    const float* Wat   = (const float*)d_in[8];
    const float* bat   = (const float*)d_in[9];
    const float* Wout  = (const float*)d_in[10];
    const float* bout  = (const float*)d_in[11];
    float* out = (float*)d_out;

    float *pv, *poff, *pattn, *psamp;
    cudaGetSymbolAddress((void**)&pv,    g_v);
    cudaGetSymbolAddress((void**)&poff,  g_off);
    cudaGetSymbolAddress((void**)&pattn, g_attn);
    cudaGetSymbolAddress((void**)&psamp, g_samp);

    const int mtiles = (MROWS + 127) / 128;  // 279

    // 1) value projection
    sgemm_kernel<1, 0><<<dim3(2, mtiles), 256>>>(value, Wv, bv, pv, MROWS, 256, 256);
    // 2) offsets
    sgemm_kernel<1, 0><<<dim3(2, mtiles), 256>>>(query, Woff, boff, poff, MROWS, 256, 256);
    // 3) attn logits
    sgemm_kernel<1, 0><<<dim3(1, mtiles), 256>>>(query, Wat, bat, pattn, MROWS, 128, 256);
    // 4) softmax + bilinear sampling (warp = (b,q,4 heads))
    const int nwarps = MROWS * 2;
    sample_kernel<<<(nwarps + 7) / 8, 256>>>(refp);
    // 5) output projection, stored transposed to (Lq, B, E)
    sgemm_kernel<0, 1><<<dim3(2, mtiles), 256>>>(psamp, Wout, bout, out, MROWS, 256, 256);
}

// round 3
// speedup vs baseline: 3.7301x; 2.1519x over previous
#include <cuda_runtime.h>
#include <cuda_bf16.h>
#include <math.h>
#include <stdint.h>

// ---------------- problem constants (static per reference) ----------------
constexpr int B_   = 2;
constexpr int E_   = 256;
constexpr int NH_  = 8;
constexpr int D_   = 32;
constexpr int NL_  = 4;
constexpr int NP_  = 4;
constexpr int LQ_  = 17821;          // == Lin
constexpr int MROWS = B_ * LQ_;      // 35642

// level geometry
__device__ __constant__ int c_HS[4] = {100, 50, 25, 13};
__device__ __constant__ int c_WS[4] = {134, 67, 34, 17};
__device__ __constant__ int c_ST[4] = {0, 13400, 16750, 17600};

// ---------------- scratch (device globals; no allocation) -----------------
__device__ float g_v[(size_t)MROWS * 256];     // projected value (b,pos,h,d)
__device__ float g_off[(size_t)MROWS * 256];   // raw offsets per (b,q)
__device__ float g_attn[(size_t)MROWS * 128];  // raw attn logits per (b,q)
__device__ float g_samp[(size_t)MROWS * 256];  // sampled output (b,q,h,d)

// ---------------------------------------------------------------------------
__device__ __forceinline__ uint32_t f2tf(float f) {
    uint32_t r;
    asm("cvt.rna.tf32.f32 %0, %1;" : "=r"(r) : "f"(f));
    return r;
}

__device__ __forceinline__ void mma_tf32(float (&d)[4], const uint32_t (&a)[4],
                                         const uint32_t (&b)[2]) {
    asm volatile(
        "mma.sync.aligned.m16n8k8.row.col.f32.tf32.tf32.f32 "
        "{%0,%1,%2,%3}, {%4,%5,%6,%7}, {%8,%9}, {%0,%1,%2,%3};"
        : "+f"(d[0]), "+f"(d[1]), "+f"(d[2]), "+f"(d[3])
        : "r"(a[0]), "r"(a[1]), "r"(a[2]), "r"(a[3]), "r"(b[0]), "r"(b[1]));
}

// ---------------------------------------------------------------------------
// TF32 tensor-core GEMM: C[M,N] = A[M,K] @ W[K,N] + bias[N]
// AMODE 0: A row m at A[m*K + k]
// AMODE 1: A is (rows, B_, K) with m = b*LQ_ + r -> A[(r*B_ + b)*K + k]
// CMODE 0 / 1 analogous for C.
// BM=128, BN=128, BK=32, 256 threads (8 warps 2x4), warp tile 64x32.
// Requires: N % 128 == 0, K % 32 == 0.
// ---------------------------------------------------------------------------
template <int AMODE, int CMODE>
__global__ void __launch_bounds__(256, 2)
tgemm_kernel(const float* __restrict__ A, const float* __restrict__ W,
             const float* __restrict__ bias, float* __restrict__ C,
             int M, int N, int K)
{
    constexpr int BM = 128, BN = 128, BK = 32;
    __shared__ uint32_t As[BM][36];    // stride 36 -> banks 4g+c conflict-free
    __shared__ uint32_t Bs[BK][136];   // stride 136 -> banks 8c+g conflict-free

    const int tid  = threadIdx.x;
    const int lane = tid & 31;
    const int warp = tid >> 5;
    const int bm = blockIdx.y * BM;
    const int bn = blockIdx.x * BN;
    const int wm = (warp & 1) * 64;    // warp m-offset (2 warps in m)
    const int wn = (warp >> 1) * 32;   // warp n-offset (4 warps in n)
    const int g  = lane >> 2;          // group id (0..7)
    const int tg = lane & 3;           // thread in group (0..3)

    // A loader: 4 passes of 32 rows; row = p*32 + tid/8, k4 = (tid&7)*4
    const int la_row = tid >> 3;
    const int la_k   = (tid & 7) * 4;
    const float* aptr[4];
#pragma unroll
    for (int p = 0; p < 4; p++) {
        int m = bm + p * 32 + la_row;
        if (m < M) {
            int off;
            if (AMODE == 0) off = m * K;
            else { int r = m % LQ_; int b = m / LQ_; off = (r * B_ + b) * K; }
            aptr[p] = A + off + la_k;
        } else aptr[p] = nullptr;
    }
    // B loader: 4 passes of 8 k-rows; k = p*8 + tid/32, n4 = (tid&31)*4
    const int lb_k = tid >> 5;
    const int lb_n = (tid & 31) * 4;

    float acc[4][4][4];
#pragma unroll
    for (int mt = 0; mt < 4; mt++)
#pragma unroll
        for (int nt = 0; nt < 4; nt++)
#pragma unroll
            for (int i = 0; i < 4; i++) acc[mt][nt][i] = 0.f;

    for (int k0 = 0; k0 < K; k0 += BK) {
#pragma unroll
        for (int p = 0; p < 4; p++) {
            float4 v = make_float4(0.f, 0.f, 0.f, 0.f);
            if (aptr[p]) v = *reinterpret_cast<const float4*>(aptr[p] + k0);
            const int row = p * 32 + la_row;
            As[row][la_k + 0] = f2tf(v.x);
            As[row][la_k + 1] = f2tf(v.y);
            As[row][la_k + 2] = f2tf(v.z);
            As[row][la_k + 3] = f2tf(v.w);
        }
#pragma unroll
        for (int p = 0; p < 4; p++) {
            const int k = p * 8 + lb_k;
            float4 v = *reinterpret_cast<const float4*>(W + (k0 + k) * N + bn + lb_n);
            Bs[k][lb_n + 0] = f2tf(v.x);
            Bs[k][lb_n + 1] = f2tf(v.y);
            Bs[k][lb_n + 2] = f2tf(v.z);
            Bs[k][lb_n + 3] = f2tf(v.w);
        }
        __syncthreads();

#pragma unroll
        for (int kk = 0; kk < 4; kk++) {
            const int kb = kk * 8;
            uint32_t af[4][4];
            uint32_t bf[4][2];
#pragma unroll
            for (int mt = 0; mt < 4; mt++) {
                const int row = wm + mt * 16 + g;
                af[mt][0] = As[row][kb + tg];
                af[mt][1] = As[row + 8][kb + tg];
                af[mt][2] = As[row][kb + tg + 4];
                af[mt][3] = As[row + 8][kb + tg + 4];
            }
#pragma unroll
            for (int nt = 0; nt < 4; nt++) {
                const int col = wn + nt * 8 + g;
                bf[nt][0] = Bs[kb + tg][col];
                bf[nt][1] = Bs[kb + tg + 4][col];
            }
#pragma unroll
            for (int mt = 0; mt < 4; mt++)
#pragma unroll
                for (int nt = 0; nt < 4; nt++)
                    mma_tf32(acc[mt][nt], af[mt], bf[nt]);
        }
        __syncthreads();
    }

    // epilogue: bias + store (c0,c1) at row r0, (c2,c3) at r0+8, cols 2*tg,2*tg+1
#pragma unroll
    for (int mt = 0; mt < 4; mt++) {
        const int r0 = bm + wm + mt * 16 + g;
        const int r1 = r0 + 8;
#pragma unroll
        for (int nt = 0; nt < 4; nt++) {
            const int col = bn + wn + nt * 8 + 2 * tg;
            const float2 bb = *reinterpret_cast<const float2*>(bias + col);
            if (r0 < M) {
                int cbase;
                if (CMODE == 0) cbase = r0 * N;
                else { int r = r0 % LQ_; int b = r0 / LQ_; cbase = (r * B_ + b) * N; }
                float2 o; o.x = acc[mt][nt][0] + bb.x; o.y = acc[mt][nt][1] + bb.y;
                *reinterpret_cast<float2*>(C + cbase + col) = o;
            }
            if (r1 < M) {
                int cbase;
                if (CMODE == 0) cbase = r1 * N;
                else { int r = r1 % LQ_; int b = r1 / LQ_; cbase = (r * B_ + b) * N; }
                float2 o; o.x = acc[mt][nt][2] + bb.x; o.y = acc[mt][nt][3] + bb.y;
                *reinterpret_cast<float2*>(C + cbase + col) = o;
            }
        }
    }
}

// ---------------------------------------------------------------------------
// Sampling kernel: one warp per (b,q,half); each 8-lane group = one head,
// lane handles float4 of D. 32-bit indexing throughout.
// ---------------------------------------------------------------------------
__global__ void __launch_bounds__(256)
sample_kernel(const float* __restrict__ refp)
{
    const int w = blockIdx.x * 8 + (threadIdx.x >> 5);
    if (w >= MROWS * 2) return;
    const int lane = threadIdx.x & 31;
    const int m    = w >> 1;              // b*Lq + q
    const int half = w & 1;
    const int g    = lane >> 3;           // head group within warp
    const int sub  = lane & 7;            // float4 slot within head (D/4 = 8)
    const int h    = half * 4 + g;
    const int b    = (m >= LQ_) ? 1 : 0;

    const float4 offv = *reinterpret_cast<const float4*>(&g_off[m * 256 + h * 32 + sub * 4]);
    const float2 lg   = *reinterpret_cast<const float2*>(&g_attn[m * 128 + h * 16 + sub * 2]);

    float mx = fmaxf(lg.x, lg.y);
    mx = fmaxf(mx, __shfl_xor_sync(0xffffffffu, mx, 1));
    const float e0 = expf(lg.x - mx);
    const float e1 = expf(lg.y - mx);
    float s = e0 + e1;
    s += __shfl_xor_sync(0xffffffffu, s, 1);
    const float inv = 1.f / s;
    const float wg0 = e0 * inv;
    const float wg1 = e1 * inv;

    float rx[4], ry[4];
#pragma unroll
    for (int l = 0; l < 4; l++) {
        rx[l] = __ldg(&refp[(m * 4 + l) * 2 + 0]);
        ry[l] = __ldg(&refp[(m * 4 + l) * 2 + 1]);
    }

    const float4* __restrict__ v4 = reinterpret_cast<const float4*>(g_v);
    int base[4];
#pragma unroll
    for (int l = 0; l < 4; l++)
        base[l] = (b * LQ_ + c_ST[l]) * 64 + h * 8 + sub;

    float4 acc = make_float4(0.f, 0.f, 0.f, 0.f);
    const int grp = lane & 24;

#pragma unroll
    for (int sp = 0; sp < 16; sp++) {
        const int l = sp >> 2;
        const int owner = grp | (sp >> 1);
        const float ox = __shfl_sync(0xffffffffu, (sp & 1) ? offv.z : offv.x, owner);
        const float oy = __shfl_sync(0xffffffffu, (sp & 1) ? offv.w : offv.y, owner);
        const float aw = __shfl_sync(0xffffffffu, (sp & 1) ? wg1 : wg0, owner);

        const int Wl = c_WS[l], Hl = c_HS[l];
        const float x = fmaf(rx[l], (float)Wl, ox) - 0.5f;
        const float y = fmaf(ry[l], (float)Hl, oy) - 0.5f;
        const float xf = floorf(x), yf = floorf(y);
        const int x0 = (int)xf, y0 = (int)yf;
        const float dx = x - xf, dy = y - yf;

        float w11 = dx * dy * aw;
        float w10 = fmaf(dx, aw, -w11);
        float w01 = fmaf(dy, aw, -w11);
        float w00 = aw - w10 - w01 - w11;

        const bool vx0 = (unsigned)x0       < (unsigned)Wl;
        const bool vx1 = (unsigned)(x0 + 1) < (unsigned)Wl;
        const bool vy0 = (unsigned)y0       < (unsigned)Hl;
        const bool vy1 = (unsigned)(y0 + 1) < (unsigned)Hl;
        if (!(vx0 && vy0)) w00 = 0.f;
        if (!(vx1 && vy0)) w10 = 0.f;
        if (!(vx0 && vy1)) w01 = 0.f;
        if (!(vx1 && vy1)) w11 = 0.f;

        const int x0c = min(max(x0, 0), Wl - 1);
        const int x1c = min(max(x0 + 1, 0), Wl - 1);
        const int y0c = min(max(y0, 0), Hl - 1);
        const int y1c = min(max(y0 + 1, 0), Hl - 1);

        const int r0 = base[l] + y0c * (Wl * 64);
        const int r1 = base[l] + y1c * (Wl * 64);

        const float4 v00 = __ldg(&v4[r0 + x0c * 64]);
        const float4 v10 = __ldg(&v4[r0 + x1c * 64]);
        const float4 v01 = __ldg(&v4[r1 + x0c * 64]);
        const float4 v11 = __ldg(&v4[r1 + x1c * 64]);

        acc.x = fmaf(w00, v00.x, acc.x); acc.y = fmaf(w00, v00.y, acc.y);
        acc.z = fmaf(w00, v00.z, acc.z); acc.w = fmaf(w00, v00.w, acc.w);
        acc.x = fmaf(w10, v10.x, acc.x); acc.y = fmaf(w10, v10.y, acc.y);
        acc.z = fmaf(w10, v10.z, acc.z); acc.w = fmaf(w10, v10.w, acc.w);
        acc.x = fmaf(w01, v01.x, acc.x); acc.y = fmaf(w01, v01.y, acc.y);
        acc.z = fmaf(w01, v01.z, acc.z); acc.w = fmaf(w01, v01.w, acc.w);
        acc.x = fmaf(w11, v11.x, acc.x); acc.y = fmaf(w11, v11.y, acc.y);
        acc.z = fmaf(w11, v11.z, acc.z); acc.w = fmaf(w11, v11.w, acc.w);
    }

    *reinterpret_cast<float4*>(&g_samp[m * 256 + h * 32 + sub * 4]) = acc;
}

// ---------------------------------------------------------------------------
extern "C" void kernel_launch(void* const* d_in, const int* in_sizes, int n_in,
                              void* d_out, int out_size)
{
    const float* query = (const float*)d_in[0];   // (Lq, B, E)
    const float* value = (const float*)d_in[1];   // (Lin, B, E)
    const float* refp  = (const float*)d_in[2];   // (B, Lq, NL, 2)
    // d_in[3] = spatial_shapes (int64) — static, hardcoded
    const float* Wv    = (const float*)d_in[4];
    const float* bv    = (const float*)d_in[5];
    const float* Woff  = (const float*)d_in[6];
    const float* boff  = (const float*)d_in[7];
    const float* Wat   = (const float*)d_in[8];
    const float* bat   = (const float*)d_in[9];
    const float* Wout  = (const float*)d_in[10];
    const float* bout  = (const float*)d_in[11];
    float* out = (float*)d_out;

    float *pv, *poff, *pattn, *psamp;
    cudaGetSymbolAddress((void**)&pv,    g_v);
    cudaGetSymbolAddress((void**)&poff,  g_off);
    cudaGetSymbolAddress((void**)&pattn, g_attn);
    cudaGetSymbolAddress((void**)&psamp, g_samp);

    const int mtiles = (MROWS + 127) / 128;  // 279

    // 1) value projection
    tgemm_kernel<1, 0><<<dim3(2, mtiles), 256>>>(value, Wv, bv, pv, MROWS, 256, 256);
    // 2) offsets
    tgemm_kernel<1, 0><<<dim3(2, mtiles), 256>>>(query, Woff, boff, poff, MROWS, 256, 256);
    // 3) attn logits
    tgemm_kernel<1, 0><<<dim3(1, mtiles), 256>>>(query, Wat, bat, pattn, MROWS, 128, 256);
    // 4) softmax + bilinear sampling (warp = (b,q,4 heads))
    const int nwarps = MROWS * 2;
    sample_kernel<<<(nwarps + 7) / 8, 256>>>(refp);
    // 5) output projection, stored transposed to (Lq, B, E)
    tgemm_kernel<0, 1><<<dim3(2, mtiles), 256>>>(psamp, Wout, bout, out, MROWS, 256, 256);
}